// round 2
// baseline (speedup 1.0000x reference)
#include <cuda_runtime.h>
#include <cstddef>

#define T_LEN 2048
#define BB 2
#define E_DIM 1024
#define H_NUM 16
#define D_HEAD 64
#define M_MEM 1024
#define NEGINF -1e9f

// ---------------- scratch (device globals; allocation-free) ----------------
__device__ float g_q [(size_t)BB * H_NUM * T_LEN * D_HEAD];   // 16 MB
__device__ float g_k [(size_t)BB * H_NUM * T_LEN * D_HEAD];   // 16 MB
__device__ float g_v [(size_t)BB * H_NUM * T_LEN * D_HEAD];   // 16 MB
__device__ float g_km[(size_t)BB * H_NUM * M_MEM * D_HEAD];   //  8 MB
__device__ float g_vm[(size_t)BB * H_NUM * M_MEM * D_HEAD];   //  8 MB
__device__ float g_ctx[(size_t)T_LEN * BB * E_DIM];           // 16 MB

// ---------------- SGEMM: C = A * W^T + bias, optional layout scatter ------
// A: [Mrows, 1024] row-major.  W: [1024, 1024] row-major (out-feature major,
// i.e. y[r,c] = sum_e A[r,e] * W[c,e]).
// MODE 0: out[r*1024 + c] = (acc + bias[c]) * scale
// MODE 1: r -> (t = r/BB, b = r%BB), c -> (h = c/64, d = c%64);
//         out[((b*H + h)*Lrows + t)*64 + d] = (acc + bias[c]) * scale
template <int MODE>
__global__ void __launch_bounds__(256)
sgemm_k(const float* __restrict__ A, const float* __restrict__ W,
        const float* __restrict__ bias, float* __restrict__ out,
        float scale, int Lrows)
{
    __shared__ float As[8][128];
    __shared__ float Bs[8][128];

    const int tid  = threadIdx.x;
    const int tx   = tid & 15;
    const int ty   = tid >> 4;
    const int row0 = blockIdx.y * 128;
    const int col0 = blockIdx.x * 128;
    const int lr   = tid >> 1;
    const int lk   = (tid & 1) * 4;

    float acc[8][8];
#pragma unroll
    for (int i = 0; i < 8; i++)
#pragma unroll
        for (int j = 0; j < 8; j++) acc[i][j] = 0.f;

    const float* Ap = A + (size_t)(row0 + lr) * E_DIM + lk;
    const float* Wp = W + (size_t)(col0 + lr) * E_DIM + lk;

    for (int kt = 0; kt < E_DIM; kt += 8) {
        const float4 av = *(const float4*)(Ap + kt);
        const float4 wv = *(const float4*)(Wp + kt);
        __syncthreads();
        As[lk + 0][lr] = av.x; As[lk + 1][lr] = av.y;
        As[lk + 2][lr] = av.z; As[lk + 3][lr] = av.w;
        Bs[lk + 0][lr] = wv.x; Bs[lk + 1][lr] = wv.y;
        Bs[lk + 2][lr] = wv.z; Bs[lk + 3][lr] = wv.w;
        __syncthreads();
#pragma unroll
        for (int k = 0; k < 8; k++) {
            const float4 a0 = *(const float4*)&As[k][ty * 4];
            const float4 a1 = *(const float4*)&As[k][64 + ty * 4];
            const float4 b0 = *(const float4*)&Bs[k][tx * 4];
            const float4 b1 = *(const float4*)&Bs[k][64 + tx * 4];
            const float ar[8] = {a0.x, a0.y, a0.z, a0.w, a1.x, a1.y, a1.z, a1.w};
            const float br[8] = {b0.x, b0.y, b0.z, b0.w, b1.x, b1.y, b1.z, b1.w};
#pragma unroll
            for (int i = 0; i < 8; i++)
#pragma unroll
                for (int j = 0; j < 8; j++) acc[i][j] += ar[i] * br[j];
        }
    }

#pragma unroll
    for (int i = 0; i < 8; i++) {
        const int r = row0 + ((i < 4) ? (ty * 4 + i) : (64 + ty * 4 + i - 4));
#pragma unroll
        for (int j = 0; j < 8; j++) {
            const int c = col0 + ((j < 4) ? (tx * 4 + j) : (64 + tx * 4 + j - 4));
            const float val = (acc[i][j] + bias[c]) * scale;
            if (MODE == 0) {
                out[(size_t)r * E_DIM + c] = val;
            } else {
                const int t = r / BB, b = r % BB;
                const int h = c >> 6, d = c & 63;
                out[(((size_t)b * H_NUM + h) * Lrows + t) * D_HEAD + d] = val;
            }
        }
    }
}

// ---------------- attention (flash-style, 64x64 tiles) --------------------
// LOCAL=true : causal + position encoding, writes (1-g)*out into ctx
// LOCAL=false: memory attention, ctx += g*out
template <bool LOCAL>
__global__ void __launch_bounds__(256)
attn_k(const float* __restrict__ Qg, const float* __restrict__ Kg,
       const float* __restrict__ Vg, const float* __restrict__ pos,
       const float* __restrict__ memb, float* __restrict__ ctx, int Skeys)
{
    extern __shared__ float sm[];
    float* Qs   = sm;              // [64][68]   (t rows, d cols)
    float* Ktd  = Qs  + 64 * 68;   // [64][68]   (d rows, s cols)  transposed
    float* Vs   = Ktd + 64 * 68;   // [64][68]   (s rows, d cols)
    float* Ss   = Vs  + 64 * 68;   // [64][68]   (t rows, s cols)
    float* mrow = Ss  + 64 * 68;   // [64]
    float* lrow = mrow + 64;       // [64]
    float* srow = lrow + 64;       // [64]

    const int tid = threadIdx.x;
    const int tx  = tid & 15;
    const int ty  = tid >> 4;
    const int h   = blockIdx.y;
    const int b   = blockIdx.z;
    const int t0  = blockIdx.x * 64;
    const size_t qbase  = (((size_t)b * H_NUM + h) * T_LEN + t0) * D_HEAD;
    const size_t kvbase = ((size_t)b * H_NUM + h) * (size_t)Skeys * D_HEAD;

    // load Q tile
    for (int i = tid; i < 64 * 16; i += 256) {
        const int r = i >> 4, c4 = (i & 15) * 4;
        *(float4*)(Qs + r * 68 + c4) = *(const float4*)(Qg + qbase + r * 64 + c4);
    }
    if (tid < 64) { mrow[tid] = -1e30f; lrow[tid] = 0.f; }

    float O[4][4];
#pragma unroll
    for (int i = 0; i < 4; i++)
#pragma unroll
        for (int j = 0; j < 4; j++) O[i][j] = 0.f;

    const int send = LOCAL ? (t0 + 64) : Skeys;
    for (int s0 = 0; s0 < send; s0 += 64) {
        __syncthreads();
        // load K (transposed into Ktd) and V tiles
        for (int i = tid; i < 64 * 16; i += 256) {
            const int r = i >> 4, c4 = (i & 15) * 4;
            const float4 kv = *(const float4*)(Kg + kvbase + (size_t)(s0 + r) * 64 + c4);
            Ktd[(c4 + 0) * 68 + r] = kv.x;
            Ktd[(c4 + 1) * 68 + r] = kv.y;
            Ktd[(c4 + 2) * 68 + r] = kv.z;
            Ktd[(c4 + 3) * 68 + r] = kv.w;
            *(float4*)(Vs + r * 68 + c4) = *(const float4*)(Vg + kvbase + (size_t)(s0 + r) * 64 + c4);
        }
        __syncthreads();

        // S = Q * K^T  (4x4 per thread)
        float Sacc[4][4];
#pragma unroll
        for (int i = 0; i < 4; i++)
#pragma unroll
            for (int j = 0; j < 4; j++) Sacc[i][j] = 0.f;

#pragma unroll 8
        for (int d = 0; d < 64; d++) {
            float a[4];
#pragma unroll
            for (int i = 0; i < 4; i++) a[i] = Qs[(ty * 4 + i) * 68 + d];
            const float4 bv = *(const float4*)(Ktd + d * 68 + tx * 4);
#pragma unroll
            for (int i = 0; i < 4; i++) {
                Sacc[i][0] += a[i] * bv.x;
                Sacc[i][1] += a[i] * bv.y;
                Sacc[i][2] += a[i] * bv.z;
                Sacc[i][3] += a[i] * bv.w;
            }
        }

        // write S to smem, fusing position encoding + causal mask
#pragma unroll
        for (int i = 0; i < 4; i++) {
            const int tr = t0 + ty * 4 + i;
            float vv[4] = {Sacc[i][0], Sacc[i][1], Sacc[i][2], Sacc[i][3]};
            if (LOCAL) {
                const float4 pv = *(const float4*)(pos + ((size_t)h * T_LEN + tr) * (size_t)T_LEN
                                                   + s0 + tx * 4);
                vv[0] += pv.x; vv[1] += pv.y; vv[2] += pv.z; vv[3] += pv.w;
#pragma unroll
                for (int j = 0; j < 4; j++)
                    if (s0 + tx * 4 + j > tr) vv[j] = NEGINF;
            }
#pragma unroll
            for (int j = 0; j < 4; j++)
                Ss[(ty * 4 + i) * 68 + tx * 4 + j] = vv[j];
        }
        __syncthreads();

        // online softmax: one thread per query row
        if (tid < 64) {
            float* srs = Ss + tid * 68;
            const float m_old = mrow[tid];
            float m = m_old;
            for (int c = 0; c < 64; c++) m = fmaxf(m, srs[c]);
            const float sc = __expf(m_old - m);
            float sum = 0.f;
            for (int c = 0; c < 64; c++) {
                const float p = __expf(srs[c] - m);
                srs[c] = p;
                sum += p;
            }
            mrow[tid] = m;
            lrow[tid] = lrow[tid] * sc + sum;
            srow[tid] = sc;
        }
        __syncthreads();

        // rescale accumulators and O += P * V
        float f[4];
#pragma unroll
        for (int i = 0; i < 4; i++) f[i] = srow[ty * 4 + i];
#pragma unroll
        for (int i = 0; i < 4; i++)
#pragma unroll
            for (int j = 0; j < 4; j++) O[i][j] *= f[i];

#pragma unroll 8
        for (int s = 0; s < 64; s++) {
            float a[4];
#pragma unroll
            for (int i = 0; i < 4; i++) a[i] = Ss[(ty * 4 + i) * 68 + s];
            const float4 bv = *(const float4*)(Vs + s * 68 + tx * 4);
#pragma unroll
            for (int i = 0; i < 4; i++) {
                O[i][0] += a[i] * bv.x;
                O[i][1] += a[i] * bv.y;
                O[i][2] += a[i] * bv.z;
                O[i][3] += a[i] * bv.w;
            }
        }
    }

    // epilogue: normalize, gate, write to ctx [T, B, E]
    const float gate = 1.f / (1.f + __expf(-memb[h]));
    const float w = LOCAL ? (1.f - gate) : gate;
    float linv[4];
#pragma unroll
    for (int i = 0; i < 4; i++) linv[i] = w / lrow[ty * 4 + i];

#pragma unroll
    for (int i = 0; i < 4; i++) {
        const int t = t0 + ty * 4 + i;
#pragma unroll
        for (int j = 0; j < 4; j++) {
            const int c = h * 64 + tx * 4 + j;
            const size_t idx = ((size_t)t * BB + b) * E_DIM + c;
            const float val = O[i][j] * linv[i];
            if (LOCAL) ctx[idx] = val;
            else       ctx[idx] += val;
        }
    }
}

// ---------------- launch ---------------------------------------------------
extern "C" void kernel_launch(void* const* d_in, const int* in_sizes, int n_in,
                              void* d_out, int out_size)
{
    const float* query = (const float*)d_in[0];
    const float* pos   = (const float*)d_in[1];
    const float* lcr   = (const float*)d_in[2];
    const float* q_w   = (const float*)d_in[3];
    const float* q_b   = (const float*)d_in[4];
    const float* k_w   = (const float*)d_in[5];
    const float* k_b   = (const float*)d_in[6];
    const float* v_w   = (const float*)d_in[7];
    const float* v_b   = (const float*)d_in[8];
    const float* out_w = (const float*)d_in[9];
    const float* out_b = (const float*)d_in[10];
    const float* memb  = (const float*)d_in[11];
    float* out = (float*)d_out;

    float *qp, *kp, *vp, *kmp, *vmp, *ctxp;
    cudaGetSymbolAddress((void**)&qp,   g_q);
    cudaGetSymbolAddress((void**)&kp,   g_k);
    cudaGetSymbolAddress((void**)&vp,   g_v);
    cudaGetSymbolAddress((void**)&kmp,  g_km);
    cudaGetSymbolAddress((void**)&vmp,  g_vm);
    cudaGetSymbolAddress((void**)&ctxp, g_ctx);

    const dim3 tpb(256);
    const float qscale = 0.125f;  // D^-0.5

    // projections
    const dim3 gq(E_DIM / 128, (T_LEN * BB) / 128);
    sgemm_k<1><<<gq, tpb>>>(query, q_w, q_b, qp, qscale, T_LEN);
    sgemm_k<1><<<gq, tpb>>>(query, k_w, k_b, kp, 1.f, T_LEN);
    sgemm_k<1><<<gq, tpb>>>(query, v_w, v_b, vp, 1.f, T_LEN);
    const dim3 gm(E_DIM / 128, (M_MEM * BB) / 128);
    sgemm_k<1><<<gm, tpb>>>(lcr,                              k_w, k_b, kmp, 1.f, M_MEM);
    sgemm_k<1><<<gm, tpb>>>(lcr + (size_t)M_MEM * BB * E_DIM, v_w, v_b, vmp, 1.f, M_MEM);

    // attention
    const int smem = (4 * 64 * 68 + 3 * 64) * (int)sizeof(float);  // 70400 B
    cudaFuncSetAttribute(attn_k<true>,  cudaFuncAttributeMaxDynamicSharedMemorySize, smem);
    cudaFuncSetAttribute(attn_k<false>, cudaFuncAttributeMaxDynamicSharedMemorySize, smem);
    const dim3 ga(T_LEN / 64, H_NUM, BB);
    attn_k<true ><<<ga, tpb, smem>>>(qp, kp,  vp,  pos, memb, ctxp, T_LEN);
    attn_k<false><<<ga, tpb, smem>>>(qp, kmp, vmp, pos, memb, ctxp, M_MEM);

    // output projection
    const dim3 go(E_DIM / 128, (T_LEN * BB) / 128);
    sgemm_k<0><<<go, tpb>>>(ctxp, out_w, out_b, out, 1.f, T_LEN);
}

// round 3
// speedup vs baseline: 1.7445x; 1.7445x over previous
#include <cuda_runtime.h>
#include <cstddef>
#include <cstdint>

#define T_LEN 2048
#define BB 2
#define E_DIM 1024
#define H_NUM 16
#define D_HEAD 64
#define M_MEM 1024
#define NEGINF -1e9f

// ---------------- scratch (device globals; allocation-free) ----------------
__device__ float g_q [(size_t)BB * H_NUM * T_LEN * D_HEAD];
__device__ float g_k [(size_t)BB * H_NUM * T_LEN * D_HEAD];
__device__ float g_v [(size_t)BB * H_NUM * T_LEN * D_HEAD];
__device__ float g_km[(size_t)BB * H_NUM * M_MEM * D_HEAD];
__device__ float g_vm[(size_t)BB * H_NUM * M_MEM * D_HEAD];
__device__ float g_ctx[(size_t)T_LEN * BB * E_DIM];

// ---------------- tf32 helpers ---------------------------------------------
__device__ __forceinline__ float f2tf(float f) {
    uint32_t u;
    asm("cvt.rna.tf32.f32 %0, %1;" : "=r"(u) : "f"(f));
    return __uint_as_float(u);
}

__device__ __forceinline__ void mma_tf32(float* c, const uint32_t* a, const uint32_t* b) {
    asm volatile(
        "mma.sync.aligned.m16n8k8.row.col.f32.tf32.tf32.f32 "
        "{%0,%1,%2,%3}, {%4,%5,%6,%7}, {%8,%9}, {%0,%1,%2,%3};"
        : "+f"(c[0]), "+f"(c[1]), "+f"(c[2]), "+f"(c[3])
        : "r"(a[0]), "r"(a[1]), "r"(a[2]), "r"(a[3]), "r"(b[0]), "r"(b[1]));
}

// ---------------- tf32 tensor-core GEMM: C = A * W^T + bias ----------------
// A: [Mrows, 1024] row-major (k contiguous).  W: [1024, 1024] row-major
// (out-feature major, k contiguous) -> B operand is natively col-major.
// MODE 0: out[r*1024 + c] = (acc + bias[c]) * scale
// MODE 1: r -> (t=r/BB, b=r%BB), c -> (h=c/64, d=c%64);
//         out[((b*H + h)*Lrows + t)*64 + d] = (acc + bias[c]) * scale
template <int MODE>
__global__ void __launch_bounds__(256)
gemm_tc(const float* __restrict__ A, const float* __restrict__ W,
        const float* __restrict__ bias, float* __restrict__ out,
        float scale, int Lrows)
{
    __shared__ float As[128][36];   // [m][k], pad 4 -> frag banks 4g+t conflict-free
    __shared__ float Bs[128][36];   // [n][k]

    const int tid  = threadIdx.x;
    const int warp = tid >> 5;
    const int lane = tid & 31;
    const int g = lane >> 2, t = lane & 3;
    const int wm = warp >> 2;       // 0..1  (64-row warp tile)
    const int wn = warp & 3;        // 0..3  (32-col warp tile)
    const int row0 = blockIdx.y * 128;
    const int col0 = blockIdx.x * 128;

    const int lr = tid >> 1;          // 0..127
    const int lc = (tid & 1) * 16;    // 0 or 16

    float acc[4][4][4];
#pragma unroll
    for (int mt = 0; mt < 4; mt++)
#pragma unroll
        for (int nt = 0; nt < 4; nt++)
#pragma unroll
            for (int i = 0; i < 4; i++) acc[mt][nt][i] = 0.f;

    const float* Ap = A + (size_t)(row0 + lr) * E_DIM + lc;
    const float* Wp = W + (size_t)(col0 + lr) * E_DIM + lc;

    for (int kt = 0; kt < E_DIM; kt += 32) {
        float4 av[4], wv[4];
#pragma unroll
        for (int i = 0; i < 4; i++) {
            av[i] = *(const float4*)(Ap + kt + i * 4);
            wv[i] = *(const float4*)(Wp + kt + i * 4);
        }
        __syncthreads();
#pragma unroll
        for (int i = 0; i < 4; i++) {
            As[lr][lc + i * 4 + 0] = f2tf(av[i].x);
            As[lr][lc + i * 4 + 1] = f2tf(av[i].y);
            As[lr][lc + i * 4 + 2] = f2tf(av[i].z);
            As[lr][lc + i * 4 + 3] = f2tf(av[i].w);
            Bs[lr][lc + i * 4 + 0] = f2tf(wv[i].x);
            Bs[lr][lc + i * 4 + 1] = f2tf(wv[i].y);
            Bs[lr][lc + i * 4 + 2] = f2tf(wv[i].z);
            Bs[lr][lc + i * 4 + 3] = f2tf(wv[i].w);
        }
        __syncthreads();

#pragma unroll
        for (int kk = 0; kk < 32; kk += 8) {
            uint32_t af[4][4], bf[4][2];
#pragma unroll
            for (int mt = 0; mt < 4; mt++) {
                const int m = wm * 64 + mt * 16;
                af[mt][0] = __float_as_uint(As[m + g    ][kk + t    ]);
                af[mt][1] = __float_as_uint(As[m + g + 8][kk + t    ]);
                af[mt][2] = __float_as_uint(As[m + g    ][kk + t + 4]);
                af[mt][3] = __float_as_uint(As[m + g + 8][kk + t + 4]);
            }
#pragma unroll
            for (int nt = 0; nt < 4; nt++) {
                const int n = wn * 32 + nt * 8;
                bf[nt][0] = __float_as_uint(Bs[n + g][kk + t    ]);
                bf[nt][1] = __float_as_uint(Bs[n + g][kk + t + 4]);
            }
#pragma unroll
            for (int mt = 0; mt < 4; mt++)
#pragma unroll
                for (int nt = 0; nt < 4; nt++)
                    mma_tf32(acc[mt][nt], af[mt], bf[nt]);
        }
    }

#pragma unroll
    for (int mt = 0; mt < 4; mt++) {
#pragma unroll
        for (int nt = 0; nt < 4; nt++) {
#pragma unroll
            for (int i = 0; i < 2; i++) {
#pragma unroll
                for (int j = 0; j < 2; j++) {
                    const int r = row0 + wm * 64 + mt * 16 + g + i * 8;
                    const int c = col0 + wn * 32 + nt * 8 + 2 * t + j;
                    const float val = (acc[mt][nt][i * 2 + j] + bias[c]) * scale;
                    if (MODE == 0) {
                        out[(size_t)r * E_DIM + c] = val;
                    } else {
                        const int tt = r / BB, b = r % BB;
                        const int h = c >> 6, d = c & 63;
                        out[(((size_t)b * H_NUM + h) * Lrows + tt) * D_HEAD + d] = val;
                    }
                }
            }
        }
    }
}

// ---------------- attention (flash-style, tf32 tensor cores) --------------
// 64 queries x 64 keys per tile.  8 warps: warp w owns an 8-wide n-slice
// (S: key cols [8w,8w+8);  PV: d cols [8w,8w+8)).
template <bool LOCAL>
__global__ void __launch_bounds__(256)
attn_tc(const float* __restrict__ Qg, const float* __restrict__ Kg,
        const float* __restrict__ Vg, const float* __restrict__ pos,
        const float* __restrict__ memb, float* __restrict__ ctx, int Skeys)
{
    extern __shared__ float sm[];
    float* Qs   = sm;              // [64][68]  tf32  (t, d)
    float* Ks   = Qs  + 64 * 68;   // [64][68]  tf32  (s, d)
    float* Vt   = Ks  + 64 * 68;   // [64][68]  tf32  (d, s)  transposed
    float* Ss   = Vt  + 64 * 68;   // [64][68]  S fp32 then P tf32 (t, s)
    float* mrow = Ss  + 64 * 68;   // [64]
    float* lrow = mrow + 64;       // [64]
    float* srow = lrow + 64;       // [64]

    const int tid  = threadIdx.x;
    const int warp = tid >> 5;
    const int lane = tid & 31;
    const int g = lane >> 2, t = lane & 3;
    const int h  = blockIdx.y;
    const int b  = blockIdx.z;
    const int t0 = blockIdx.x * 64;
    const size_t qbase  = (((size_t)b * H_NUM + h) * T_LEN + t0) * D_HEAD;
    const size_t kvbase = ((size_t)b * H_NUM + h) * (size_t)Skeys * D_HEAD;

    // load Q tile (tf32-rounded)
    for (int i = tid; i < 64 * 16; i += 256) {
        const int r = i >> 4, c4 = (i & 15) * 4;
        const float4 qv = *(const float4*)(Qg + qbase + r * 64 + c4);
        float4 qt = make_float4(f2tf(qv.x), f2tf(qv.y), f2tf(qv.z), f2tf(qv.w));
        *(float4*)(Qs + r * 68 + c4) = qt;
    }
    if (tid < 64) { mrow[tid] = -1e30f; lrow[tid] = 0.f; }

    float O[4][4];
#pragma unroll
    for (int mt = 0; mt < 4; mt++)
#pragma unroll
        for (int i = 0; i < 4; i++) O[mt][i] = 0.f;

    const int send = LOCAL ? (t0 + 64) : Skeys;
    for (int s0 = 0; s0 < send; s0 += 64) {
        __syncthreads();
        // load K tile and V tile (transposed), tf32-rounded
        for (int i = tid; i < 64 * 16; i += 256) {
            const int r = i >> 4, c4 = (i & 15) * 4;
            const float4 kv = *(const float4*)(Kg + kvbase + (size_t)(s0 + r) * 64 + c4);
            *(float4*)(Ks + r * 68 + c4) =
                make_float4(f2tf(kv.x), f2tf(kv.y), f2tf(kv.z), f2tf(kv.w));
            const float4 vv = *(const float4*)(Vg + kvbase + (size_t)(s0 + r) * 64 + c4);
            Vt[(c4 + 0) * 68 + r] = f2tf(vv.x);
            Vt[(c4 + 1) * 68 + r] = f2tf(vv.y);
            Vt[(c4 + 2) * 68 + r] = f2tf(vv.z);
            Vt[(c4 + 3) * 68 + r] = f2tf(vv.w);
        }
        __syncthreads();

        // ---- S = Q K^T (warp: n-slice = key cols [8w, 8w+8)) ----
        float Sacc[4][4];
#pragma unroll
        for (int mt = 0; mt < 4; mt++)
#pragma unroll
            for (int i = 0; i < 4; i++) Sacc[mt][i] = 0.f;

#pragma unroll
        for (int kk = 0; kk < 64; kk += 8) {
            uint32_t bf[2];
            bf[0] = __float_as_uint(Ks[(warp * 8 + g) * 68 + kk + t    ]);
            bf[1] = __float_as_uint(Ks[(warp * 8 + g) * 68 + kk + t + 4]);
#pragma unroll
            for (int mt = 0; mt < 4; mt++) {
                uint32_t af[4];
                const int m = mt * 16;
                af[0] = __float_as_uint(Qs[(m + g    ) * 68 + kk + t    ]);
                af[1] = __float_as_uint(Qs[(m + g + 8) * 68 + kk + t    ]);
                af[2] = __float_as_uint(Qs[(m + g    ) * 68 + kk + t + 4]);
                af[3] = __float_as_uint(Qs[(m + g + 8) * 68 + kk + t + 4]);
                mma_tf32(Sacc[mt], af, bf);
            }
        }

        // write S to smem, fusing position encoding + causal mask
#pragma unroll
        for (int mt = 0; mt < 4; mt++) {
#pragma unroll
            for (int i = 0; i < 2; i++) {
                const int r = mt * 16 + g + i * 8;
                const int c = warp * 8 + 2 * t;
                float v0 = Sacc[mt][i * 2 + 0];
                float v1 = Sacc[mt][i * 2 + 1];
                if (LOCAL) {
                    const int tr = t0 + r;
                    const float2 pv = *(const float2*)(pos
                        + ((size_t)h * T_LEN + tr) * (size_t)T_LEN + s0 + c);
                    v0 += pv.x; v1 += pv.y;
                    if (s0 + c     > tr) v0 = NEGINF;
                    if (s0 + c + 1 > tr) v1 = NEGINF;
                }
                Ss[r * 68 + c]     = v0;
                Ss[r * 68 + c + 1] = v1;
            }
        }
        __syncthreads();

        // ---- online softmax: warp w owns rows [8w, 8w+8), 4 lanes per row ----
        {
            const int row = warp * 8 + g;
            float* srs = Ss + row * 68 + t * 16;
            const float m_old = mrow[row];
            float m = m_old;
#pragma unroll
            for (int c = 0; c < 16; c++) m = fmaxf(m, srs[c]);
            m = fmaxf(m, __shfl_xor_sync(0xffffffffu, m, 1));
            m = fmaxf(m, __shfl_xor_sync(0xffffffffu, m, 2));
            float sum = 0.f;
#pragma unroll
            for (int c = 0; c < 16; c++) {
                const float p = __expf(srs[c] - m);
                sum += p;
                srs[c] = f2tf(p);
            }
            sum += __shfl_xor_sync(0xffffffffu, sum, 1);
            sum += __shfl_xor_sync(0xffffffffu, sum, 2);
            const float sc = __expf(m_old - m);
            if (t == 0) {
                mrow[row] = m;
                lrow[row] = lrow[row] * sc + sum;
                srow[row] = sc;
            }
        }
        __syncthreads();

        // ---- rescale O, then O += P V (warp: n-slice = d cols [8w, 8w+8)) ----
#pragma unroll
        for (int mt = 0; mt < 4; mt++) {
            const float f0 = srow[mt * 16 + g];
            const float f1 = srow[mt * 16 + g + 8];
            O[mt][0] *= f0; O[mt][1] *= f0;
            O[mt][2] *= f1; O[mt][3] *= f1;
        }
#pragma unroll
        for (int kk = 0; kk < 64; kk += 8) {
            uint32_t bf[2];
            bf[0] = __float_as_uint(Vt[(warp * 8 + g) * 68 + kk + t    ]);
            bf[1] = __float_as_uint(Vt[(warp * 8 + g) * 68 + kk + t + 4]);
#pragma unroll
            for (int mt = 0; mt < 4; mt++) {
                uint32_t af[4];
                const int m = mt * 16;
                af[0] = __float_as_uint(Ss[(m + g    ) * 68 + kk + t    ]);
                af[1] = __float_as_uint(Ss[(m + g + 8) * 68 + kk + t    ]);
                af[2] = __float_as_uint(Ss[(m + g    ) * 68 + kk + t + 4]);
                af[3] = __float_as_uint(Ss[(m + g + 8) * 68 + kk + t + 4]);
                mma_tf32(O[mt], af, bf);
            }
        }
    }

    // epilogue: normalize, gate, write to ctx [T, B, E]
    const float gate = 1.f / (1.f + __expf(-memb[h]));
    const float wgt  = LOCAL ? (1.f - gate) : gate;
#pragma unroll
    for (int mt = 0; mt < 4; mt++) {
#pragma unroll
        for (int i = 0; i < 2; i++) {
            const int row = mt * 16 + g + i * 8;
            const float linv = wgt / lrow[row];
            const int tg = t0 + row;
#pragma unroll
            for (int j = 0; j < 2; j++) {
                const int c = h * 64 + warp * 8 + 2 * t + j;
                const size_t idx = ((size_t)tg * BB + b) * E_DIM + c;
                const float val = O[mt][i * 2 + j] * linv;
                if (LOCAL) ctx[idx] = val;
                else       ctx[idx] += val;
            }
        }
    }
}

// ---------------- launch ---------------------------------------------------
extern "C" void kernel_launch(void* const* d_in, const int* in_sizes, int n_in,
                              void* d_out, int out_size)
{
    const float* query = (const float*)d_in[0];
    const float* pos   = (const float*)d_in[1];
    const float* lcr   = (const float*)d_in[2];
    const float* q_w   = (const float*)d_in[3];
    const float* q_b   = (const float*)d_in[4];
    const float* k_w   = (const float*)d_in[5];
    const float* k_b   = (const float*)d_in[6];
    const float* v_w   = (const float*)d_in[7];
    const float* v_b   = (const float*)d_in[8];
    const float* out_w = (const float*)d_in[9];
    const float* out_b = (const float*)d_in[10];
    const float* memb  = (const float*)d_in[11];
    float* out = (float*)d_out;

    float *qp, *kp, *vp, *kmp, *vmp, *ctxp;
    cudaGetSymbolAddress((void**)&qp,   g_q);
    cudaGetSymbolAddress((void**)&kp,   g_k);
    cudaGetSymbolAddress((void**)&vp,   g_v);
    cudaGetSymbolAddress((void**)&kmp,  g_km);
    cudaGetSymbolAddress((void**)&vmp,  g_vm);
    cudaGetSymbolAddress((void**)&ctxp, g_ctx);

    const dim3 tpb(256);
    const float qscale = 0.125f;  // D^-0.5

    // projections (tensor cores)
    const dim3 gq(E_DIM / 128, (T_LEN * BB) / 128);
    gemm_tc<1><<<gq, tpb>>>(query, q_w, q_b, qp, qscale, T_LEN);
    gemm_tc<1><<<gq, tpb>>>(query, k_w, k_b, kp, 1.f, T_LEN);
    gemm_tc<1><<<gq, tpb>>>(query, v_w, v_b, vp, 1.f, T_LEN);
    const dim3 gm(E_DIM / 128, (M_MEM * BB) / 128);
    gemm_tc<1><<<gm, tpb>>>(lcr,                              k_w, k_b, kmp, 1.f, M_MEM);
    gemm_tc<1><<<gm, tpb>>>(lcr + (size_t)M_MEM * BB * E_DIM, v_w, v_b, vmp, 1.f, M_MEM);

    // attention (tensor cores)
    const int smem = (4 * 64 * 68 + 3 * 64) * (int)sizeof(float);  // 70400 B
    cudaFuncSetAttribute(attn_tc<true>,  cudaFuncAttributeMaxDynamicSharedMemorySize, smem);
    cudaFuncSetAttribute(attn_tc<false>, cudaFuncAttributeMaxDynamicSharedMemorySize, smem);
    const dim3 ga(T_LEN / 64, H_NUM, BB);
    attn_tc<true ><<<ga, tpb, smem>>>(qp, kp,  vp,  pos, memb, ctxp, T_LEN);
    attn_tc<false><<<ga, tpb, smem>>>(qp, kmp, vmp, pos, memb, ctxp, M_MEM);

    // output projection
    const dim3 go(E_DIM / 128, (T_LEN * BB) / 128);
    gemm_tc<0><<<go, tpb>>>(ctxp, out_w, out_b, out, 1.f, T_LEN);
}

// round 7
// speedup vs baseline: 1.9438x; 1.1143x over previous
#include <cuda_runtime.h>
#include <cstddef>
#include <cstdint>

#define T_LEN 2048
#define BB 2
#define E_DIM 1024
#define H_NUM 16
#define D_HEAD 64
#define M_MEM 1024
#define NEGINF -1e9f

// ---------------- scratch (device globals; allocation-free) ----------------
__device__ float g_q [(size_t)BB * H_NUM * T_LEN * D_HEAD];
__device__ float g_k [(size_t)BB * H_NUM * T_LEN * D_HEAD];
__device__ float g_v [(size_t)BB * H_NUM * T_LEN * D_HEAD];
__device__ float g_km[(size_t)BB * H_NUM * M_MEM * D_HEAD];
__device__ float g_vm[(size_t)BB * H_NUM * M_MEM * D_HEAD];
__device__ float g_ctx[(size_t)T_LEN * BB * E_DIM];

// ---------------- tf32 helpers ---------------------------------------------
__device__ __forceinline__ float f2tf(float f) {
    uint32_t u;
    asm("cvt.rna.tf32.f32 %0, %1;" : "=r"(u) : "f"(f));
    return __uint_as_float(u);
}

__device__ __forceinline__ void mma_tf32(float* c, const uint32_t* a, const uint32_t* b) {
    asm volatile(
        "mma.sync.aligned.m16n8k8.row.col.f32.tf32.tf32.f32 "
        "{%0,%1,%2,%3}, {%4,%5,%6,%7}, {%8,%9}, {%0,%1,%2,%3};"
        : "+f"(c[0]), "+f"(c[1]), "+f"(c[2]), "+f"(c[3])
        : "r"(a[0]), "r"(a[1]), "r"(a[2]), "r"(a[3]), "r"(b[0]), "r"(b[1]));
}

// ---------------- tf32 GEMM, 2-stage pipelined: C = A * W^T + bias --------
// A: [Mrows,1024] row-major. W: [1024,1024] row-major (out-feature major).
// MODE 0: out[r*1024+c];  MODE 1: scatter to [B,H,L,D].
#define GEMM_STG (128 * 36)
template <int MODE>
__global__ void __launch_bounds__(256)
gemm_tc(const float* __restrict__ A, const float* __restrict__ W,
        const float* __restrict__ bias, float* __restrict__ out,
        float scale, int Lrows)
{
    extern __shared__ float gsm[];
    // As[stage][128][36], Bs[stage][128][36]
    float* Asb = gsm;
    float* Bsb = gsm + 2 * GEMM_STG;

    const int tid  = threadIdx.x;
    const int warp = tid >> 5;
    const int lane = tid & 31;
    const int g = lane >> 2, t = lane & 3;
    const int wm = warp >> 2;
    const int wn = warp & 3;
    const int row0 = blockIdx.y * 128;
    const int col0 = blockIdx.x * 128;

    const int lr = tid >> 1;
    const int lc = (tid & 1) * 16;

    float acc[4][4][4];
#pragma unroll
    for (int mt = 0; mt < 4; mt++)
#pragma unroll
        for (int nt = 0; nt < 4; nt++)
#pragma unroll
            for (int i = 0; i < 4; i++) acc[mt][nt][i] = 0.f;

    const float* Ap = A + (size_t)(row0 + lr) * E_DIM + lc;
    const float* Wp = W + (size_t)(col0 + lr) * E_DIM + lc;

    // prologue: load + stage chunk 0
    float4 av[4], wv[4];
#pragma unroll
    for (int i = 0; i < 4; i++) { av[i] = *(const float4*)(Ap + i * 4);
                                  wv[i] = *(const float4*)(Wp + i * 4); }
    {
        float* As = Asb; float* Bs = Bsb;
#pragma unroll
        for (int i = 0; i < 4; i++) {
            As[lr * 36 + lc + i*4 + 0] = f2tf(av[i].x);
            As[lr * 36 + lc + i*4 + 1] = f2tf(av[i].y);
            As[lr * 36 + lc + i*4 + 2] = f2tf(av[i].z);
            As[lr * 36 + lc + i*4 + 3] = f2tf(av[i].w);
            Bs[lr * 36 + lc + i*4 + 0] = f2tf(wv[i].x);
            Bs[lr * 36 + lc + i*4 + 1] = f2tf(wv[i].y);
            Bs[lr * 36 + lc + i*4 + 2] = f2tf(wv[i].z);
            Bs[lr * 36 + lc + i*4 + 3] = f2tf(wv[i].w);
        }
    }
    __syncthreads();

    for (int kt = 0; kt < E_DIM; kt += 32) {
        const int cur = (kt >> 5) & 1;
        const int nxt = cur ^ 1;
        const bool more = (kt + 32) < E_DIM;
        if (more) {
#pragma unroll
            for (int i = 0; i < 4; i++) {
                av[i] = *(const float4*)(Ap + kt + 32 + i * 4);
                wv[i] = *(const float4*)(Wp + kt + 32 + i * 4);
            }
        }

        const float* As = Asb + cur * GEMM_STG;
        const float* Bs = Bsb + cur * GEMM_STG;
#pragma unroll
        for (int kk = 0; kk < 32; kk += 8) {
            uint32_t af[4][4], bf[4][2];
#pragma unroll
            for (int mt = 0; mt < 4; mt++) {
                const int m = wm * 64 + mt * 16;
                af[mt][0] = __float_as_uint(As[(m + g    ) * 36 + kk + t    ]);
                af[mt][1] = __float_as_uint(As[(m + g + 8) * 36 + kk + t    ]);
                af[mt][2] = __float_as_uint(As[(m + g    ) * 36 + kk + t + 4]);
                af[mt][3] = __float_as_uint(As[(m + g + 8) * 36 + kk + t + 4]);
            }
#pragma unroll
            for (int nt = 0; nt < 4; nt++) {
                const int n = wn * 32 + nt * 8;
                bf[nt][0] = __float_as_uint(Bs[(n + g) * 36 + kk + t    ]);
                bf[nt][1] = __float_as_uint(Bs[(n + g) * 36 + kk + t + 4]);
            }
#pragma unroll
            for (int mt = 0; mt < 4; mt++)
#pragma unroll
                for (int nt = 0; nt < 4; nt++)
                    mma_tf32(acc[mt][nt], af[mt], bf[nt]);
        }

        if (more) {
            float* Asn = Asb + nxt * GEMM_STG;
            float* Bsn = Bsb + nxt * GEMM_STG;
#pragma unroll
            for (int i = 0; i < 4; i++) {
                Asn[lr * 36 + lc + i*4 + 0] = f2tf(av[i].x);
                Asn[lr * 36 + lc + i*4 + 1] = f2tf(av[i].y);
                Asn[lr * 36 + lc + i*4 + 2] = f2tf(av[i].z);
                Asn[lr * 36 + lc + i*4 + 3] = f2tf(av[i].w);
                Bsn[lr * 36 + lc + i*4 + 0] = f2tf(wv[i].x);
                Bsn[lr * 36 + lc + i*4 + 1] = f2tf(wv[i].y);
                Bsn[lr * 36 + lc + i*4 + 2] = f2tf(wv[i].z);
                Bsn[lr * 36 + lc + i*4 + 3] = f2tf(wv[i].w);
            }
        }
        __syncthreads();
    }

#pragma unroll
    for (int mt = 0; mt < 4; mt++) {
#pragma unroll
        for (int nt = 0; nt < 4; nt++) {
#pragma unroll
            for (int i = 0; i < 2; i++) {
#pragma unroll
                for (int j = 0; j < 2; j++) {
                    const int r = row0 + wm * 64 + mt * 16 + g + i * 8;
                    const int c = col0 + wn * 32 + nt * 8 + 2 * t + j;
                    const float val = (acc[mt][nt][i * 2 + j] + bias[c]) * scale;
                    if (MODE == 0) {
                        out[(size_t)r * E_DIM + c] = val;
                    } else {
                        const int tt = r / BB, b = r % BB;
                        const int h = c >> 6, d = c & 63;
                        out[(((size_t)b * H_NUM + h) * Lrows + tt) * D_HEAD + d] = val;
                    }
                }
            }
        }
    }
}

// ---------------- attention: FA2-style, warp-owned query rows --------------
// CTA: 128 queries, 8 warps; warp w owns rows [16w, 16w+16). Key tile = 64.
// Q in registers (A-frags). Softmax fully in registers (quad shuffles).
// P re-shaped through warp-private smem for the PV MMA.
template <bool LOCAL>
__global__ void __launch_bounds__(256, 1)
attn_fa(const float* __restrict__ Qg, const float* __restrict__ Kg,
        const float* __restrict__ Vg, const float* __restrict__ pos,
        const float* __restrict__ memb, float* __restrict__ ctx, int Skeys)
{
    extern __shared__ float sm[];
    float* Ks = sm;                 // [64][68]  (s, d) tf32
    float* Vt = Ks + 64 * 68;       // [64][68]  (d, s) tf32 transposed
    float* Ps = Vt + 64 * 68;       // 8 x [16][68] per-warp P buffer

    const int tid  = threadIdx.x;
    const int warp = tid >> 5;
    const int lane = tid & 31;
    const int g = lane >> 2, t = lane & 3;
    const int h  = blockIdx.y;
    const int b  = blockIdx.z;
    const int t0 = blockIdx.x * 128;
    const int qrow = t0 + warp * 16;
    const size_t qbase  = (((size_t)b * H_NUM + h) * T_LEN + qrow) * D_HEAD;
    const size_t kvbase = ((size_t)b * H_NUM + h) * (size_t)Skeys * D_HEAD;
    float* Pw = Ps + warp * 16 * 68;

    // Q fragments in registers (loaded once)
    uint32_t qf[8][4];
#pragma unroll
    for (int kk8 = 0; kk8 < 8; kk8++) {
        const int k = kk8 * 8;
        qf[kk8][0] = __float_as_uint(f2tf(__ldg(Qg + qbase + (size_t)g       * 64 + k + t    )));
        qf[kk8][1] = __float_as_uint(f2tf(__ldg(Qg + qbase + (size_t)(g + 8) * 64 + k + t    )));
        qf[kk8][2] = __float_as_uint(f2tf(__ldg(Qg + qbase + (size_t)g       * 64 + k + t + 4)));
        qf[kk8][3] = __float_as_uint(f2tf(__ldg(Qg + qbase + (size_t)(g + 8) * 64 + k + t + 4)));
    }

    float m0 = -1e30f, m1 = -1e30f;   // running max, rows g and g+8
    float l0 = 0.f, l1 = 0.f;         // per-thread partial sums
    float O[8][4];
#pragma unroll
    for (int nt = 0; nt < 8; nt++)
#pragma unroll
        for (int i = 0; i < 4; i++) O[nt][i] = 0.f;

    const int send = LOCAL ? (t0 + 128) : Skeys;
    for (int s0 = 0; s0 < send; s0 += 64) {
        __syncthreads();   // all warps done reading previous K/V tile
        for (int i = tid; i < 64 * 16; i += 256) {
            const int r = i >> 4, c4 = (i & 15) * 4;
            const float4 kv = *(const float4*)(Kg + kvbase + (size_t)(s0 + r) * 64 + c4);
            *(float4*)(Ks + r * 68 + c4) =
                make_float4(f2tf(kv.x), f2tf(kv.y), f2tf(kv.z), f2tf(kv.w));
            const float4 vv = *(const float4*)(Vg + kvbase + (size_t)(s0 + r) * 64 + c4);
            Vt[(c4 + 0) * 68 + r] = f2tf(vv.x);
            Vt[(c4 + 1) * 68 + r] = f2tf(vv.y);
            Vt[(c4 + 2) * 68 + r] = f2tf(vv.z);
            Vt[(c4 + 3) * 68 + r] = f2tf(vv.w);
        }
        __syncthreads();

        // ---- S = Q K^T : 8 n-tiles x 8 k-steps ----
        float Sa[8][4];
#pragma unroll
        for (int nt = 0; nt < 8; nt++)
#pragma unroll
            for (int i = 0; i < 4; i++) Sa[nt][i] = 0.f;
#pragma unroll
        for (int kk8 = 0; kk8 < 8; kk8++) {
            const int kk = kk8 * 8;
#pragma unroll
            for (int nt = 0; nt < 8; nt++) {
                uint32_t bf[2];
                bf[0] = __float_as_uint(Ks[(nt * 8 + g) * 68 + kk + t    ]);
                bf[1] = __float_as_uint(Ks[(nt * 8 + g) * 68 + kk + t + 4]);
                mma_tf32(Sa[nt], qf[kk8], bf);
            }
        }

        // ---- position encoding + causal mask (register-resident) ----
        if (LOCAL) {
            const int r0 = qrow + g, r1 = qrow + g + 8;
            const size_t pb0 = ((size_t)h * T_LEN + r0) * (size_t)T_LEN + s0;
            const size_t pb1 = ((size_t)h * T_LEN + r1) * (size_t)T_LEN + s0;
#pragma unroll
            for (int nt = 0; nt < 8; nt++) {
                const int c = nt * 8 + 2 * t;
                const float2 p0 = *(const float2*)(pos + pb0 + c);
                const float2 p1 = *(const float2*)(pos + pb1 + c);
                Sa[nt][0] += p0.x; Sa[nt][1] += p0.y;
                Sa[nt][2] += p1.x; Sa[nt][3] += p1.y;
                const int gc = s0 + c;
                if (gc     > r0) Sa[nt][0] = NEGINF;
                if (gc + 1 > r0) Sa[nt][1] = NEGINF;
                if (gc     > r1) Sa[nt][2] = NEGINF;
                if (gc + 1 > r1) Sa[nt][3] = NEGINF;
            }
        }

        // ---- online softmax in registers ----
        float mn0 = m0, mn1 = m1;
#pragma unroll
        for (int nt = 0; nt < 8; nt++) {
            mn0 = fmaxf(mn0, fmaxf(Sa[nt][0], Sa[nt][1]));
            mn1 = fmaxf(mn1, fmaxf(Sa[nt][2], Sa[nt][3]));
        }
        mn0 = fmaxf(mn0, __shfl_xor_sync(0xffffffffu, mn0, 1));
        mn0 = fmaxf(mn0, __shfl_xor_sync(0xffffffffu, mn0, 2));
        mn1 = fmaxf(mn1, __shfl_xor_sync(0xffffffffu, mn1, 1));
        mn1 = fmaxf(mn1, __shfl_xor_sync(0xffffffffu, mn1, 2));
        const float sc0 = __expf(m0 - mn0);
        const float sc1 = __expf(m1 - mn1);
        m0 = mn0; m1 = mn1;
        float sum0 = 0.f, sum1 = 0.f;
#pragma unroll
        for (int nt = 0; nt < 8; nt++) {
            float p0 = __expf(Sa[nt][0] - m0);
            float p1 = __expf(Sa[nt][1] - m0);
            float p2 = __expf(Sa[nt][2] - m1);
            float p3 = __expf(Sa[nt][3] - m1);
            sum0 += p0 + p1; sum1 += p2 + p3;
            Sa[nt][0] = f2tf(p0); Sa[nt][1] = f2tf(p1);
            Sa[nt][2] = f2tf(p2); Sa[nt][3] = f2tf(p3);
        }
        l0 = l0 * sc0 + sum0;
        l1 = l1 * sc1 + sum1;

        // rescale O
#pragma unroll
        for (int nt = 0; nt < 8; nt++) {
            O[nt][0] *= sc0; O[nt][1] *= sc0;
            O[nt][2] *= sc1; O[nt][3] *= sc1;
        }

        // ---- store P to warp-private smem (reshape to A-frag layout) ----
        __syncwarp();
#pragma unroll
        for (int nt = 0; nt < 8; nt++) {
            const int c = nt * 8 + 2 * t;
            *(float2*)(Pw + g       * 68 + c) = make_float2(Sa[nt][0], Sa[nt][1]);
            *(float2*)(Pw + (g + 8) * 68 + c) = make_float2(Sa[nt][2], Sa[nt][3]);
        }
        __syncwarp();

        // ---- O += P V ----
#pragma unroll
        for (int kk8 = 0; kk8 < 8; kk8++) {
            const int kk = kk8 * 8;
            uint32_t af[4];
            af[0] = __float_as_uint(Pw[(g    ) * 68 + kk + t    ]);
            af[1] = __float_as_uint(Pw[(g + 8) * 68 + kk + t    ]);
            af[2] = __float_as_uint(Pw[(g    ) * 68 + kk + t + 4]);
            af[3] = __float_as_uint(Pw[(g + 8) * 68 + kk + t + 4]);
#pragma unroll
            for (int nt = 0; nt < 8; nt++) {
                uint32_t bf[2];
                bf[0] = __float_as_uint(Vt[(nt * 8 + g) * 68 + kk + t    ]);
                bf[1] = __float_as_uint(Vt[(nt * 8 + g) * 68 + kk + t + 4]);
                mma_tf32(O[nt], af, bf);
            }
        }
    }

    // ---- epilogue: reduce l across quad, normalize, gate, write ctx ----
    l0 += __shfl_xor_sync(0xffffffffu, l0, 1);
    l0 += __shfl_xor_sync(0xffffffffu, l0, 2);
    l1 += __shfl_xor_sync(0xffffffffu, l1, 1);
    l1 += __shfl_xor_sync(0xffffffffu, l1, 2);

    const float gate = 1.f / (1.f + __expf(-memb[h]));
    const float wgt  = LOCAL ? (1.f - gate) : gate;
    const float li0 = wgt / l0;
    const float li1 = wgt / l1;

    const int r0 = qrow + g, r1 = qrow + g + 8;
#pragma unroll
    for (int nt = 0; nt < 8; nt++) {
        const int c = h * 64 + nt * 8 + 2 * t;
        const size_t i0 = ((size_t)r0 * BB + b) * E_DIM + c;
        const size_t i1 = ((size_t)r1 * BB + b) * E_DIM + c;
        if (LOCAL) {
            *(float2*)(ctx + i0) = make_float2(O[nt][0] * li0, O[nt][1] * li0);
            *(float2*)(ctx + i1) = make_float2(O[nt][2] * li1, O[nt][3] * li1);
        } else {
            ctx[i0]     += O[nt][0] * li0;
            ctx[i0 + 1] += O[nt][1] * li0;
            ctx[i1]     += O[nt][2] * li1;
            ctx[i1 + 1] += O[nt][3] * li1;
        }
    }
}

// ---------------- launch ---------------------------------------------------
extern "C" void kernel_launch(void* const* d_in, const int* in_sizes, int n_in,
                              void* d_out, int out_size)
{
    const float* query = (const float*)d_in[0];
    const float* pos   = (const float*)d_in[1];
    const float* lcr   = (const float*)d_in[2];
    const float* q_w   = (const float*)d_in[3];
    const float* q_b   = (const float*)d_in[4];
    const float* k_w   = (const float*)d_in[5];
    const float* k_b   = (const float*)d_in[6];
    const float* v_w   = (const float*)d_in[7];
    const float* v_b   = (const float*)d_in[8];
    const float* out_w = (const float*)d_in[9];
    const float* out_b = (const float*)d_in[10];
    const float* memb  = (const float*)d_in[11];
    float* out = (float*)d_out;

    float *qp, *kp, *vp, *kmp, *vmp, *ctxp;
    cudaGetSymbolAddress((void**)&qp,   g_q);
    cudaGetSymbolAddress((void**)&kp,   g_k);
    cudaGetSymbolAddress((void**)&vp,   g_v);
    cudaGetSymbolAddress((void**)&kmp,  g_km);
    cudaGetSymbolAddress((void**)&vmp,  g_vm);
    cudaGetSymbolAddress((void**)&ctxp, g_ctx);

    const dim3 tpb(256);
    const float qscale = 0.125f;  // D^-0.5

    const int gsmem = 4 * GEMM_STG * (int)sizeof(float);  // 73728 B
    cudaFuncSetAttribute(gemm_tc<0>, cudaFuncAttributeMaxDynamicSharedMemorySize, gsmem);
    cudaFuncSetAttribute(gemm_tc<1>, cudaFuncAttributeMaxDynamicSharedMemorySize, gsmem);

    // projections
    const dim3 gq(E_DIM / 128, (T_LEN * BB) / 128);
    gemm_tc<1><<<gq, tpb, gsmem>>>(query, q_w, q_b, qp, qscale, T_LEN);
    gemm_tc<1><<<gq, tpb, gsmem>>>(query, k_w, k_b, kp, 1.f, T_LEN);
    gemm_tc<1><<<gq, tpb, gsmem>>>(query, v_w, v_b, vp, 1.f, T_LEN);
    const dim3 gm(E_DIM / 128, (M_MEM * BB) / 128);
    gemm_tc<1><<<gm, tpb, gsmem>>>(lcr,                              k_w, k_b, kmp, 1.f, M_MEM);
    gemm_tc<1><<<gm, tpb, gsmem>>>(lcr + (size_t)M_MEM * BB * E_DIM, v_w, v_b, vmp, 1.f, M_MEM);

    // attention
    const int asmem = (2 * 64 * 68 + 8 * 16 * 68) * (int)sizeof(float);  // 69632 B
    cudaFuncSetAttribute(attn_fa<true>,  cudaFuncAttributeMaxDynamicSharedMemorySize, asmem);
    cudaFuncSetAttribute(attn_fa<false>, cudaFuncAttributeMaxDynamicSharedMemorySize, asmem);
    const dim3 ga(T_LEN / 128, H_NUM, BB);
    attn_fa<true ><<<ga, tpb, asmem>>>(qp, kp,  vp,  pos, memb, ctxp, T_LEN);
    attn_fa<false><<<ga, tpb, asmem>>>(qp, kmp, vmp, pos, memb, ctxp, M_MEM);

    // output projection
    const dim3 go(E_DIM / 128, (T_LEN * BB) / 128);
    gemm_tc<0><<<go, tpb, gsmem>>>(ctxp, out_w, out_b, out, 1.f, T_LEN);
}